// round 14
// baseline (speedup 1.0000x reference)
#include <cuda_runtime.h>
#include <cuda_bf16.h>
#include <cstdio>

// ---------------------------------------------------------------------------
// VisionExperts: 3 patch-embed vision towers + projectors, routed top-2 of 3.
//
// Pipeline per expert e (all launches sequential on default stream):
//   [e==1] resize input 448->336 (bilinear align_corners)
//   im2col -> padded patches [b][T][Kp]           (skip sample if weight==0)
//   tower GEMM:  feat[b][T][C]  = patches @ Wt + bt
//   proj  GEMM:  e0: out += w[b]*(feat @ Wp + bp)   (grid resize is identity)
//                e1/e2: proj[b][T][1024] = feat @ Wp + bp
//   [e!=0] combine: out[b][q][:] += w[b] * 4-tap-bilinear(proj tokens)
//
// Resize-after-projector is exact: resize is linear over tokens, GEMM is over
// channels, and bilinear weights sum to 1 so the bias passes through.
// ---------------------------------------------------------------------------

#define NB 64
#define NGRID 32
#define NHID 1024

// scratch (static device memory — no allocations anywhere)
__device__ float g_x336 [ (size_t)NB*3*336*336 ];                 //  86.7 MB
__device__ float g_patch[ (size_t)NB*1024*592  ];                 // 155  MB (max of experts)
__device__ float g_wt   [ (size_t)3072*1152    ];                 //  14  MB (padded tower weights)
__device__ float g_feat [ (size_t)NB*1024*1024 ];                 // 268  MB (max tower output)
__device__ float g_proj [ (size_t)NB*576*1024  ];                 // 151  MB (max proj output e1/e2)
__device__ float g_w    [ 3*NB ];                                  // per-expert per-sample weight

// ---------------------------------------------------------------------------
__global__ void weights_kernel(const int* __restrict__ sel,
                               const float* __restrict__ rw,
                               float* __restrict__ gw)
{
    int b = threadIdx.x;
    if (b >= NB) return;
    float w0 = 0.f, w1 = 0.f, w2 = 0.f;
#pragma unroll
    for (int j = 0; j < 2; ++j) {
        int   e = sel[b*2 + j];
        float r = rw [b*2 + j];
        if (e == 0) w0 += r; else if (e == 1) w1 += r; else w2 += r;
    }
    gw[b] = w0; gw[NB + b] = w1; gw[2*NB + b] = w2;
}

// copy tower weight [K][N] into padded [Kp][N] (zero tail rows)
__global__ void wpad_kernel(const float* __restrict__ w, float* __restrict__ dst,
                            int copyN, int total)
{
    int idx = blockIdx.x * blockDim.x + threadIdx.x;
    if (idx >= total) return;
    dst[idx] = (idx < copyN) ? w[idx] : 0.f;
}

// bilinear align_corners input resize 448 -> 336
__global__ void resize_in_kernel(const float* __restrict__ x,
                                 float* __restrict__ dst,
                                 const float* __restrict__ wgt)
{
    const int b = blockIdx.z;
    if (wgt[b] == 0.f) return;
    int idx = blockIdx.x * blockDim.x + threadIdx.x;
    const int total = 3*336*336;
    if (idx >= total) return;
    int ox = idx % 336;
    int t  = idx / 336;
    int oy = t % 336;
    int ch = t / 336;

    float ys = (float)(oy * 447) / 335.0f;
    int y0 = (int)ys; if (y0 > 447) y0 = 447;
    int y1 = y0 + 1;  if (y1 > 447) y1 = 447;
    float ty = ys - (float)y0;

    float xs = (float)(ox * 447) / 335.0f;
    int x0 = (int)xs; if (x0 > 447) x0 = 447;
    int x1 = x0 + 1;  if (x1 > 447) x1 = 447;
    float tx = xs - (float)x0;

    const float* xb = x + ((size_t)b*3 + ch) * (size_t)(448*448);
    float v00 = xb[y0*448 + x0], v01 = xb[y0*448 + x1];
    float v10 = xb[y1*448 + x0], v11 = xb[y1*448 + x1];
    float r0 = v00*(1.f-tx) + v01*tx;
    float r1 = v10*(1.f-tx) + v11*tx;
    dst[((size_t)b*3 + ch)*(size_t)(336*336) + oy*336 + ox] = r0*(1.f-ty) + r1*ty;
}

// im2col: src [B][3][S][S] -> patch [b][T][Kp]  (k = ch*P*P + py*P + px, zero pad)
__global__ void im2col_kernel(const float* __restrict__ src,
                              float* __restrict__ patch,
                              const float* __restrict__ wgt,
                              int S, int P, int G, int K, int Kp)
{
    const int b = blockIdx.z;
    if (wgt[b] == 0.f) return;
    const int T = G * G;
    const int total = T * Kp;
    int idx = blockIdx.x * blockDim.x + threadIdx.x;
    if (idx >= total) return;
    const int kk = idx % Kp;
    const int t  = idx / Kp;
    float v = 0.f;
    if (kk < K) {
        const int pp = P * P;
        const int ch = kk / pp;
        const int r  = kk - ch * pp;
        const int py = r / P, px = r - py * P;
        const int gy = t / G, gx = t - gy * G;
        v = src[(((size_t)b*3 + ch)*S + (gy*P + py)) * (size_t)S + (gx*P + px)];
    }
    patch[(size_t)b * T * Kp + idx] = v;
}

// ---------------------------------------------------------------------------
// 128x128x16 double-buffered fp32 SGEMM, 256 threads, 8x8 micro-tile.
// A: [b][M][K] row-major (K mult of 16), W: [K][N] (N mult of 128), bias: [N].
// DIRECT:  C[b][M][N] += wgt[b] * (acc + bias)
// !DIRECT: C[b][M][N]  =          (acc + bias)
// Block skips entirely when wgt[b]==0.
// ---------------------------------------------------------------------------
template<bool DIRECT>
__global__ void __launch_bounds__(256, 2)
sgemm_kernel(const float* __restrict__ A, const float* __restrict__ W,
             const float* __restrict__ bias, float* __restrict__ C,
             const float* __restrict__ wgt, int M, int N, int K)
{
    const int b = blockIdx.z;
    const float w = wgt[b];
    if (w == 0.f) return;
    A += (size_t)b * M * K;
    C += (size_t)b * M * N;
    const int bm = blockIdx.y * 128;
    const int bn = blockIdx.x * 128;

    __shared__ float As[2][16][132];   // [k][m], padded
    __shared__ float Bs[2][16][128];   // [k][n]

    const int tid  = threadIdx.x;
    const int arow = tid >> 2;          // 0..63  (rows arow, arow+64)
    const int acol = (tid & 3) << 2;    // 0,4,8,12
    const int brow = tid >> 5;          // 0..7   (k rows brow, brow+8)
    const int bcol = (tid & 31) << 2;   // 0..124
    const int tx = tid & 15, ty = tid >> 4;
    const int m0 = ty << 2, m1 = (ty << 2) + 64;
    const int n0 = tx << 2, n1 = (tx << 2) + 64;

    float acc[8][8];
#pragma unroll
    for (int i = 0; i < 8; ++i)
#pragma unroll
        for (int j = 0; j < 8; ++j) acc[i][j] = 0.f;

    const int r0 = min(bm + arow,      M - 1);
    const int r1 = min(bm + arow + 64, M - 1);

    float4 pa0, pa1, pb0, pb1;
    // tile 0
    pa0 = *reinterpret_cast<const float4*>(A + (size_t)r0 * K + acol);
    pa1 = *reinterpret_cast<const float4*>(A + (size_t)r1 * K + acol);
    pb0 = *reinterpret_cast<const float4*>(W + (size_t)brow       * N + bn + bcol);
    pb1 = *reinterpret_cast<const float4*>(W + (size_t)(brow + 8) * N + bn + bcol);

    As[0][acol+0][arow]    = pa0.x; As[0][acol+1][arow]    = pa0.y;
    As[0][acol+2][arow]    = pa0.z; As[0][acol+3][arow]    = pa0.w;
    As[0][acol+0][arow+64] = pa1.x; As[0][acol+1][arow+64] = pa1.y;
    As[0][acol+2][arow+64] = pa1.z; As[0][acol+3][arow+64] = pa1.w;
    *reinterpret_cast<float4*>(&Bs[0][brow][bcol])     = pb0;
    *reinterpret_cast<float4*>(&Bs[0][brow + 8][bcol]) = pb1;
    __syncthreads();

    const int KT = K >> 4;
    int buf = 0;
    for (int kt = 0; kt < KT; ++kt) {
        if (kt + 1 < KT) {
            const int k0 = (kt + 1) << 4;
            pa0 = *reinterpret_cast<const float4*>(A + (size_t)r0 * K + k0 + acol);
            pa1 = *reinterpret_cast<const float4*>(A + (size_t)r1 * K + k0 + acol);
            pb0 = *reinterpret_cast<const float4*>(W + (size_t)(k0 + brow)     * N + bn + bcol);
            pb1 = *reinterpret_cast<const float4*>(W + (size_t)(k0 + brow + 8) * N + bn + bcol);
        }
        const float (*Asb)[132] = As[buf];
        const float (*Bsb)[128] = Bs[buf];
#pragma unroll
        for (int k = 0; k < 16; ++k) {
            const float4 av0 = *reinterpret_cast<const float4*>(&Asb[k][m0]);
            const float4 av1 = *reinterpret_cast<const float4*>(&Asb[k][m1]);
            const float4 bv0 = *reinterpret_cast<const float4*>(&Bsb[k][n0]);
            const float4 bv1 = *reinterpret_cast<const float4*>(&Bsb[k][n1]);
            const float a[8] = {av0.x, av0.y, av0.z, av0.w, av1.x, av1.y, av1.z, av1.w};
            const float bb[8] = {bv0.x, bv0.y, bv0.z, bv0.w, bv1.x, bv1.y, bv1.z, bv1.w};
#pragma unroll
            for (int i = 0; i < 8; ++i)
#pragma unroll
                for (int j = 0; j < 8; ++j)
                    acc[i][j] = fmaf(a[i], bb[j], acc[i][j]);
        }
        if (kt + 1 < KT) {
            const int nb = buf ^ 1;
            As[nb][acol+0][arow]    = pa0.x; As[nb][acol+1][arow]    = pa0.y;
            As[nb][acol+2][arow]    = pa0.z; As[nb][acol+3][arow]    = pa0.w;
            As[nb][acol+0][arow+64] = pa1.x; As[nb][acol+1][arow+64] = pa1.y;
            As[nb][acol+2][arow+64] = pa1.z; As[nb][acol+3][arow+64] = pa1.w;
            *reinterpret_cast<float4*>(&Bs[nb][brow][bcol])     = pb0;
            *reinterpret_cast<float4*>(&Bs[nb][brow + 8][bcol]) = pb1;
            __syncthreads();
            buf = nb;
        }
    }

    // epilogue
    float bv[8];
#pragma unroll
    for (int j = 0; j < 4; ++j) {
        bv[j]     = bias[bn + n0 + j];
        bv[4 + j] = bias[bn + n1 + j];
    }
#pragma unroll
    for (int i = 0; i < 8; ++i) {
        const int row = bm + ((i < 4) ? (m0 + i) : (m1 + i - 4));
        if (row >= M) continue;
        float* cp = C + (size_t)row * N + bn;
        if (DIRECT) {
            float4 o0 = *reinterpret_cast<float4*>(cp + n0);
            o0.x += w * (acc[i][0] + bv[0]); o0.y += w * (acc[i][1] + bv[1]);
            o0.z += w * (acc[i][2] + bv[2]); o0.w += w * (acc[i][3] + bv[3]);
            *reinterpret_cast<float4*>(cp + n0) = o0;
            float4 o1 = *reinterpret_cast<float4*>(cp + n1);
            o1.x += w * (acc[i][4] + bv[4]); o1.y += w * (acc[i][5] + bv[5]);
            o1.z += w * (acc[i][6] + bv[6]); o1.w += w * (acc[i][7] + bv[7]);
            *reinterpret_cast<float4*>(cp + n1) = o1;
        } else {
            float4 v0 = make_float4(acc[i][0] + bv[0], acc[i][1] + bv[1],
                                    acc[i][2] + bv[2], acc[i][3] + bv[3]);
            *reinterpret_cast<float4*>(cp + n0) = v0;
            float4 v1 = make_float4(acc[i][4] + bv[4], acc[i][5] + bv[5],
                                    acc[i][6] + bv[6], acc[i][7] + bv[7]);
            *reinterpret_cast<float4*>(cp + n1) = v1;
        }
    }
}

// 4-tap bilinear token resize (GxG -> 32x32) of proj output, weighted accumulate.
__global__ void combine_kernel(const float* __restrict__ proj,
                               float* __restrict__ out,
                               const float* __restrict__ wgt, int G)
{
    const int b = blockIdx.z;
    const float w = wgt[b];
    if (w == 0.f) return;
    const int q  = blockIdx.x;
    const int oy = q >> 5, ox = q & 31;

    float ys = (float)(oy * (G - 1)) / 31.0f;
    int y0 = (int)ys; if (y0 > G - 1) y0 = G - 1;
    int y1 = y0 + 1;  if (y1 > G - 1) y1 = G - 1;
    float ty = ys - (float)y0;

    float xs = (float)(ox * (G - 1)) / 31.0f;
    int x0 = (int)xs; if (x0 > G - 1) x0 = G - 1;
    int x1 = x0 + 1;  if (x1 > G - 1) x1 = G - 1;
    float tx = xs - (float)x0;

    const float c00 = (1.f-ty)*(1.f-tx), c01 = (1.f-ty)*tx;
    const float c10 = ty*(1.f-tx),       c11 = ty*tx;

    const float4* p00 = reinterpret_cast<const float4*>(proj + ((size_t)b*G*G + y0*G + x0) * NHID);
    const float4* p01 = reinterpret_cast<const float4*>(proj + ((size_t)b*G*G + y0*G + x1) * NHID);
    const float4* p10 = reinterpret_cast<const float4*>(proj + ((size_t)b*G*G + y1*G + x0) * NHID);
    const float4* p11 = reinterpret_cast<const float4*>(proj + ((size_t)b*G*G + y1*G + x1) * NHID);
    float4* ob = reinterpret_cast<float4*>(out + ((size_t)b*1024 + q) * NHID);

    const int h = threadIdx.x;   // 256 threads x float4 = 1024 channels
    const float4 v00 = p00[h], v01 = p01[h], v10 = p10[h], v11 = p11[h];
    float4 o = ob[h];
    o.x += w * (c00*v00.x + c01*v01.x + c10*v10.x + c11*v11.x);
    o.y += w * (c00*v00.y + c01*v01.y + c10*v10.y + c11*v11.y);
    o.z += w * (c00*v00.z + c01*v01.z + c10*v10.z + c11*v11.z);
    o.w += w * (c00*v00.w + c01*v01.w + c10*v10.w + c11*v11.w);
    ob[h] = o;
}

// ---------------------------------------------------------------------------
static inline float* devPtr(const void* symbol)
{
    void* p = nullptr;
    cudaGetSymbolAddress(&p, symbol);
    return reinterpret_cast<float*>(p);
}

extern "C" void kernel_launch(void* const* d_in, const int* in_sizes, int n_in,
                              void* d_out, int out_size)
{
    const float* x   = (const float*)d_in[0];
    const int*   sel = (const int*)  d_in[1];
    const float* rw  = (const float*)d_in[2];
    const float* wt[3] = {(const float*)d_in[3],  (const float*)d_in[7],  (const float*)d_in[11]};
    const float* bt[3] = {(const float*)d_in[4],  (const float*)d_in[8],  (const float*)d_in[12]};
    const float* wp[3] = {(const float*)d_in[5],  (const float*)d_in[9],  (const float*)d_in[13]};
    const float* bp[3] = {(const float*)d_in[6],  (const float*)d_in[10], (const float*)d_in[14]};
    float* out = (float*)d_out;

    float* p_x336  = devPtr(g_x336);
    float* p_patch = devPtr(g_patch);
    float* p_wt    = devPtr(g_wt);
    float* p_feat  = devPtr(g_feat);
    float* p_proj  = devPtr(g_proj);
    float* p_w     = devPtr(g_w);

    cudaMemsetAsync(d_out, 0, (size_t)out_size * sizeof(float));
    weights_kernel<<<1, 64>>>(sel, rw, p_w);

    // ---------------- expert 0: S=448 P=14 G=32 C=1024, identity resizes ----
    {
        const int S = 448, P = 14, G = 32, C = 1024, K = 588, Kp = 592, T = G*G;
        wpad_kernel<<<(Kp*C + 255)/256, 256>>>(wt[0], p_wt, K*C, Kp*C);
        im2col_kernel<<<dim3((T*Kp + 255)/256, 1, NB), 256>>>(x, p_patch, p_w, S, P, G, K, Kp);
        sgemm_kernel<false><<<dim3(C/128, (T+127)/128, NB), 256>>>(
            p_patch, p_wt, bt[0], p_feat, p_w, T, C, Kp);
        sgemm_kernel<true><<<dim3(NHID/128, (T+127)/128, NB), 256>>>(
            p_feat, wp[0], bp[0], out, p_w, T, NHID, C);
    }

    // ---------------- expert 1: S=336 P=14 G=24 C=768 ------------------------
    {
        const int S = 336, P = 14, G = 24, C = 768, K = 588, Kp = 592, T = G*G;
        resize_in_kernel<<<dim3((3*336*336 + 255)/256, 1, NB), 256>>>(x, p_x336, p_w + NB);
        wpad_kernel<<<(Kp*C + 255)/256, 256>>>(wt[1], p_wt, K*C, Kp*C);
        im2col_kernel<<<dim3((T*Kp + 255)/256, 1, NB), 256>>>(p_x336, p_patch, p_w + NB, S, P, G, K, Kp);
        sgemm_kernel<false><<<dim3(C/128, (T+127)/128, NB), 256>>>(
            p_patch, p_wt, bt[1], p_feat, p_w + NB, T, C, Kp);
        sgemm_kernel<false><<<dim3(NHID/128, (T+127)/128, NB), 256>>>(
            p_feat, wp[1], bp[1], p_proj, p_w + NB, T, NHID, C);
        combine_kernel<<<dim3(1024, 1, NB), 256>>>(p_proj, out, p_w + NB, G);
    }

    // ---------------- expert 2: S=448 P=32 G=14 C=1152 -----------------------
    {
        const int S = 448, P = 32, G = 14, C = 1152, K = 3072, Kp = 3072, T = G*G;
        wpad_kernel<<<(Kp*C + 255)/256, 256>>>(wt[2], p_wt, K*C, Kp*C);
        im2col_kernel<<<dim3((T*Kp + 255)/256, 1, NB), 256>>>(x, p_patch, p_w + 2*NB, S, P, G, K, Kp);
        sgemm_kernel<false><<<dim3(C/128, (T+127)/128, NB), 256>>>(
            p_patch, p_wt, bt[2], p_feat, p_w + 2*NB, T, C, Kp);
        sgemm_kernel<false><<<dim3(NHID/128, (T+127)/128, NB), 256>>>(
            p_feat, wp[2], bp[2], p_proj, p_w + 2*NB, T, NHID, C);
        combine_kernel<<<dim3(1024, 1, NB), 256>>>(p_proj, out, p_w + 2*NB, G);
    }
}

// round 16
// speedup vs baseline: 2.2775x; 2.2775x over previous
#include <cuda_runtime.h>
#include <cuda_bf16.h>
#include <cstdint>

// ---------------------------------------------------------------------------
// VisionExperts: 3 patch-embed towers + projectors, routed top-2 of 3.
// GEMMs run on tensor cores via mma.sync tf32 (base-target PTX — the harness
// compiles through compute_103, which rejects tcgen05).
//   im2col (K padded to 32) -> tf32 GEMM (tower) -> tf32 GEMM (projector)
//   expert0 projector accumulates straight into out; experts 1/2 go through a
//   4-tap bilinear token combine (resize-after-projector is exact: bilinear
//   weights sum to 1 so the bias commutes through).
// ---------------------------------------------------------------------------

#define NB 64
#define NHID 1024

// scratch (static device memory — no allocations anywhere)
__device__ float g_x336 [ (size_t)NB*3*336*336 ];
__device__ float g_patch[ (size_t)NB*1024*608  ];
__device__ float g_feat [ (size_t)NB*1024*1024 ];
__device__ float g_proj [ (size_t)NB*576*1024  ];
__device__ float g_wtA  [ (size_t)3072*1152    ];   // transposed tower weight [C][Kp]
__device__ float g_wtB  [ (size_t)1024*1152    ];   // transposed proj  weight [1024][C]
__device__ float g_w    [ 3*NB ];

__device__ __forceinline__ float to_tf32(float x) {
    float r; asm("cvt.rna.tf32.f32 %0, %1;" : "=f"(r) : "f"(x)); return r;
}

#define MMA_TF32(c, a0, a1, a2, a3, b0, b1)                                        \
    asm volatile("mma.sync.aligned.m16n8k8.row.col.f32.tf32.tf32.f32 "             \
                 "{%0,%1,%2,%3},{%4,%5,%6,%7},{%8,%9},{%0,%1,%2,%3};"              \
                 : "+f"((c)[0]), "+f"((c)[1]), "+f"((c)[2]), "+f"((c)[3])          \
                 : "r"(a0), "r"(a1), "r"(a2), "r"(a3), "r"(b0), "r"(b1))

// ---------------------------------------------------------------------------
__global__ void weights_kernel(const int* __restrict__ sel,
                               const float* __restrict__ rw,
                               float* __restrict__ gw)
{
    int b = threadIdx.x;
    if (b >= NB) return;
    float w0 = 0.f, w1 = 0.f, w2 = 0.f;
#pragma unroll
    for (int j = 0; j < 2; ++j) {
        int e = sel[b*2 + j]; float r = rw[b*2 + j];
        if (e == 0) w0 += r; else if (e == 1) w1 += r; else w2 += r;
    }
    gw[b] = w0; gw[NB + b] = w1; gw[2*NB + b] = w2;
}

// transpose weight [K][N] -> [N][Kp] (zero pad k in [K,Kp))
__global__ void wtrans_kernel(const float* __restrict__ src, float* __restrict__ dst,
                              int K, int N, int Kp)
{
    __shared__ float t[32][33];
    const int k0 = blockIdx.y * 32, n0 = blockIdx.x * 32;
    const int tx = threadIdx.x, ty = threadIdx.y;
#pragma unroll
    for (int i = ty; i < 32; i += 8) {
        int k = k0 + i, n = n0 + tx;
        t[i][tx] = (k < K && n < N) ? src[(size_t)k * N + n] : 0.f;
    }
    __syncthreads();
#pragma unroll
    for (int i = ty; i < 32; i += 8) {
        int n = n0 + i, k = k0 + tx;
        if (n < N && k < Kp) dst[(size_t)n * Kp + k] = t[tx][i];
    }
}

// bilinear align_corners input resize 448 -> 336
__global__ void resize_in_kernel(const float* __restrict__ x, float* __restrict__ dst,
                                 const float* __restrict__ wgt)
{
    const int b = blockIdx.z;
    if (wgt[b] == 0.f) return;
    int idx = blockIdx.x * blockDim.x + threadIdx.x;
    if (idx >= 3*336*336) return;
    int ox = idx % 336, t = idx / 336, oy = t % 336, ch = t / 336;

    float ys = (float)(oy * 447) / 335.0f;
    int y0 = (int)ys; if (y0 > 447) y0 = 447;
    int y1 = y0 + 1;  if (y1 > 447) y1 = 447;
    float ty = ys - (float)y0;
    float xs = (float)(ox * 447) / 335.0f;
    int x0 = (int)xs; if (x0 > 447) x0 = 447;
    int x1 = x0 + 1;  if (x1 > 447) x1 = 447;
    float tx = xs - (float)x0;

    const float* xb = x + ((size_t)b*3 + ch) * (size_t)(448*448);
    float v00 = xb[y0*448 + x0], v01 = xb[y0*448 + x1];
    float v10 = xb[y1*448 + x0], v11 = xb[y1*448 + x1];
    float r0 = v00*(1.f-tx) + v01*tx;
    float r1 = v10*(1.f-tx) + v11*tx;
    dst[((size_t)b*3 + ch)*(size_t)(336*336) + oy*336 + ox] = r0*(1.f-ty) + r1*ty;
}

// im2col: src [B][3][S][S] -> patch [b][T][Kp]
__global__ void im2col_kernel(const float* __restrict__ src, float* __restrict__ patch,
                              const float* __restrict__ wgt,
                              int S, int P, int G, int K, int Kp)
{
    const int b = blockIdx.z;
    if (wgt[b] == 0.f) return;
    const int T = G * G;
    int idx = blockIdx.x * blockDim.x + threadIdx.x;
    if (idx >= T * Kp) return;
    const int kk = idx % Kp;
    const int t  = idx / Kp;
    float v = 0.f;
    if (kk < K) {
        const int pp = P * P;
        const int ch = kk / pp;
        const int r  = kk - ch * pp;
        const int py = r / P, px = r - py * P;
        const int gy = t / G, gx = t - gy * G;
        v = src[(((size_t)b*3 + ch)*S + (gy*P + py)) * (size_t)S + (gx*P + px)];
    }
    patch[(size_t)b * T * Kp + idx] = v;
}

// ---------------------------------------------------------------------------
// Tensor-core tf32 GEMM: C[b][M][N](+)= A[b][M][K] @ Bt^T + bias,  Bt: [N][K].
// Block tile 128x128xBK32, 8 warps (4Mx2N), warp tile 32x64 of m16n8k8 MMAs.
// SMEM row stride 36 floats -> conflict-free fragment loads and stores.
// DIRECT:  C += wgt[b]*(acc+bias);  else C = acc+bias. Skip CTA if wgt==0.
// K must be a multiple of 32, N a multiple of 128.
// ---------------------------------------------------------------------------
#define SM_STRIDE 36
#define BUF_FLOATS (128 * SM_STRIDE)          // 4608 floats per operand tile
#define TGEMM_SMEM (4 * BUF_FLOATS * 4)       // A0,B0,A1,B1 = 73728 bytes

template<bool DIRECT>
__global__ void __launch_bounds__(256, 2)
tgemm_kernel(const float* __restrict__ A, const float* __restrict__ Bt,
             const float* __restrict__ bias, float* __restrict__ C,
             const float* __restrict__ wgt, int M, int N, int K)
{
    const int b = blockIdx.z;
    const float w = wgt[b];
    if (w == 0.f) return;

    extern __shared__ float sm[];   // [A0][B0][A1][B1]

    A += (size_t)b * M * K;
    C += (size_t)b * M * N;
    const int bm = blockIdx.y * 128;
    const int bn = blockIdx.x * 128;

    const int tid  = threadIdx.x;
    const int lrow = tid >> 3;            // 0..31
    const int lcol = (tid & 7) << 2;      // 0,4,...,28
    const int wid  = tid >> 5, lane = tid & 31;
    const int g  = lane >> 2, t4 = lane & 3;
    const int wm = (wid >> 1) << 5;       // 0,32,64,96
    const int wn = (wid & 1) << 6;        // 0,64

    // gmem offsets (per-thread, 4 rows each spaced 32 apart); clamp A rows
    uint32_t aoff[4], boff[4];
#pragma unroll
    for (int i = 0; i < 4; ++i) {
        int ar = bm + lrow + 32*i; if (ar > M - 1) ar = M - 1;
        aoff[i] = (uint32_t)ar * (uint32_t)K + lcol;
        boff[i] = (uint32_t)(bn + lrow + 32*i) * (uint32_t)K + lcol;
    }
    const uint32_t ssto = lrow * SM_STRIDE + lcol;   // smem store offset (floats)

    float acc[2][8][4];
#pragma unroll
    for (int mi = 0; mi < 2; ++mi)
#pragma unroll
        for (int ni = 0; ni < 8; ++ni)
#pragma unroll
            for (int j = 0; j < 4; ++j) acc[mi][ni][j] = 0.f;

    float4 pa[4], pb[4];
    // tile 0
#pragma unroll
    for (int i = 0; i < 4; ++i) {
        pa[i] = *reinterpret_cast<const float4*>(A  + aoff[i]);
        pb[i] = *reinterpret_cast<const float4*>(Bt + boff[i]);
    }
#pragma unroll
    for (int i = 0; i < 4; ++i) {
        float4 va = pa[i], vb = pb[i];
        va.x = to_tf32(va.x); va.y = to_tf32(va.y); va.z = to_tf32(va.z); va.w = to_tf32(va.w);
        vb.x = to_tf32(vb.x); vb.y = to_tf32(vb.y); vb.z = to_tf32(vb.z); vb.w = to_tf32(vb.w);
        *reinterpret_cast<float4*>(sm + ssto + i*32*SM_STRIDE)                  = va;
        *reinterpret_cast<float4*>(sm + BUF_FLOATS + ssto + i*32*SM_STRIDE)    = vb;
    }
    __syncthreads();

    const int KT = K >> 5;
    for (int kt = 0; kt < KT; ++kt) {
        if (kt + 1 < KT) {
            const uint32_t kc = (uint32_t)(kt + 1) << 5;
#pragma unroll
            for (int i = 0; i < 4; ++i) {
                pa[i] = *reinterpret_cast<const float4*>(A  + aoff[i] + kc);
                pb[i] = *reinterpret_cast<const float4*>(Bt + boff[i] + kc);
            }
        }
        const float* as = sm + (kt & 1) * (2 * BUF_FLOATS);
        const float* bs = as + BUF_FLOATS;
#pragma unroll
        for (int ks = 0; ks < 4; ++ks) {
            const int k0 = ks * 8;
            uint32_t af[2][4];
#pragma unroll
            for (int mi = 0; mi < 2; ++mi) {
                const float* ap = as + (wm + mi*16 + g) * SM_STRIDE + k0 + t4;
                af[mi][0] = __float_as_uint(ap[0]);
                af[mi][1] = __float_as_uint(ap[8*SM_STRIDE]);
                af[mi][2] = __float_as_uint(ap[4]);
                af[mi][3] = __float_as_uint(ap[8*SM_STRIDE + 4]);
            }
#pragma unroll
            for (int ni = 0; ni < 8; ++ni) {
                const float* bp = bs + (wn + ni*8 + g) * SM_STRIDE + k0 + t4;
                const uint32_t b0 = __float_as_uint(bp[0]);
                const uint32_t b1 = __float_as_uint(bp[4]);
                MMA_TF32(acc[0][ni], af[0][0], af[0][1], af[0][2], af[0][3], b0, b1);
                MMA_TF32(acc[1][ni], af[1][0], af[1][1], af[1][2], af[1][3], b0, b1);
            }
        }
        if (kt + 1 < KT) {
            float* asn = sm + ((kt + 1) & 1) * (2 * BUF_FLOATS);
            float* bsn = asn + BUF_FLOATS;
#pragma unroll
            for (int i = 0; i < 4; ++i) {
                float4 va = pa[i], vb = pb[i];
                va.x = to_tf32(va.x); va.y = to_tf32(va.y); va.z = to_tf32(va.z); va.w = to_tf32(va.w);
                vb.x = to_tf32(vb.x); vb.y = to_tf32(vb.y); vb.z = to_tf32(vb.z); vb.w = to_tf32(vb.w);
                *reinterpret_cast<float4*>(asn + ssto + i*32*SM_STRIDE) = va;
                *reinterpret_cast<float4*>(bsn + ssto + i*32*SM_STRIDE) = vb;
            }
            __syncthreads();
        }
    }

    // epilogue
#pragma unroll
    for (int mi = 0; mi < 2; ++mi) {
        const int r0 = bm + wm + mi*16 + g;
        const int r1 = r0 + 8;
#pragma unroll
        for (int ni = 0; ni < 8; ++ni) {
            const int cn = bn + wn + ni*8 + (t4 << 1);
            const float bx = bias[cn], by = bias[cn + 1];
            if (r0 < M) {
                float* cp = C + (size_t)r0 * N + cn;
                if (DIRECT) {
                    float2 o = *reinterpret_cast<float2*>(cp);
                    o.x += w * (acc[mi][ni][0] + bx);
                    o.y += w * (acc[mi][ni][1] + by);
                    *reinterpret_cast<float2*>(cp) = o;
                } else {
                    float2 v = make_float2(acc[mi][ni][0] + bx, acc[mi][ni][1] + by);
                    *reinterpret_cast<float2*>(cp) = v;
                }
            }
            if (r1 < M) {
                float* cp = C + (size_t)r1 * N + cn;
                if (DIRECT) {
                    float2 o = *reinterpret_cast<float2*>(cp);
                    o.x += w * (acc[mi][ni][2] + bx);
                    o.y += w * (acc[mi][ni][3] + by);
                    *reinterpret_cast<float2*>(cp) = o;
                } else {
                    float2 v = make_float2(acc[mi][ni][2] + bx, acc[mi][ni][3] + by);
                    *reinterpret_cast<float2*>(cp) = v;
                }
            }
        }
    }
}

// 4-tap bilinear token resize (GxG -> 32x32) of proj output, weighted accumulate.
__global__ void combine_kernel(const float* __restrict__ proj, float* __restrict__ out,
                               const float* __restrict__ wgt, int G)
{
    const int b = blockIdx.z;
    const float w = wgt[b];
    if (w == 0.f) return;
    const int q = blockIdx.x;
    const int oy = q >> 5, ox = q & 31;

    float ys = (float)(oy * (G - 1)) / 31.0f;
    int y0 = (int)ys; if (y0 > G - 1) y0 = G - 1;
    int y1 = y0 + 1;  if (y1 > G - 1) y1 = G - 1;
    float ty = ys - (float)y0;
    float xs = (float)(ox * (G - 1)) / 31.0f;
    int x0 = (int)xs; if (x0 > G - 1) x0 = G - 1;
    int x1 = x0 + 1;  if (x1 > G - 1) x1 = G - 1;
    float tx = xs - (float)x0;

    const float c00 = (1.f-ty)*(1.f-tx), c01 = (1.f-ty)*tx;
    const float c10 = ty*(1.f-tx),       c11 = ty*tx;

    const float4* p00 = reinterpret_cast<const float4*>(proj + ((size_t)b*G*G + y0*G + x0) * NHID);
    const float4* p01 = reinterpret_cast<const float4*>(proj + ((size_t)b*G*G + y0*G + x1) * NHID);
    const float4* p10 = reinterpret_cast<const float4*>(proj + ((size_t)b*G*G + y1*G + x0) * NHID);
    const float4* p11 = reinterpret_cast<const float4*>(proj + ((size_t)b*G*G + y1*G + x1) * NHID);
    float4* ob = reinterpret_cast<float4*>(out + ((size_t)b*1024 + q) * NHID);

    const int h = threadIdx.x;
    const float4 v00 = p00[h], v01 = p01[h], v10 = p10[h], v11 = p11[h];
    float4 o = ob[h];
    o.x += w * (c00*v00.x + c01*v01.x + c10*v10.x + c11*v11.x);
    o.y += w * (c00*v00.y + c01*v01.y + c10*v10.y + c11*v11.y);
    o.z += w * (c00*v00.z + c01*v01.z + c10*v10.z + c11*v11.z);
    o.w += w * (c00*v00.w + c01*v01.w + c10*v10.w + c11*v11.w);
    ob[h] = o;
}

// ---------------------------------------------------------------------------
static inline float* devPtr(const void* symbol)
{
    void* p = nullptr;
    cudaGetSymbolAddress(&p, symbol);
    return reinterpret_cast<float*>(p);
}

extern "C" void kernel_launch(void* const* d_in, const int* in_sizes, int n_in,
                              void* d_out, int out_size)
{
    const float* x   = (const float*)d_in[0];
    const int*   sel = (const int*)  d_in[1];
    const float* rw  = (const float*)d_in[2];
    const float* wt[3] = {(const float*)d_in[3],  (const float*)d_in[7],  (const float*)d_in[11]};
    const float* bt[3] = {(const float*)d_in[4],  (const float*)d_in[8],  (const float*)d_in[12]};
    const float* wp[3] = {(const float*)d_in[5],  (const float*)d_in[9],  (const float*)d_in[13]};
    const float* bp[3] = {(const float*)d_in[6],  (const float*)d_in[10], (const float*)d_in[14]};
    float* out = (float*)d_out;

    float* p_x336  = devPtr(g_x336);
    float* p_patch = devPtr(g_patch);
    float* p_feat  = devPtr(g_feat);
    float* p_proj  = devPtr(g_proj);
    float* p_wtA   = devPtr(g_wtA);
    float* p_wtB   = devPtr(g_wtB);
    float* p_w     = devPtr(g_w);

    cudaFuncSetAttribute(tgemm_kernel<false>, cudaFuncAttributeMaxDynamicSharedMemorySize, TGEMM_SMEM);
    cudaFuncSetAttribute(tgemm_kernel<true>,  cudaFuncAttributeMaxDynamicSharedMemorySize, TGEMM_SMEM);

    cudaMemsetAsync(d_out, 0, (size_t)out_size * sizeof(float));
    weights_kernel<<<1, 64>>>(sel, rw, p_w);

    const dim3 tb(256);

    // ---------------- expert 0: S=448 P=14 G=32 C=1024 ----------------------
    {
        const int S=448, P=14, G=32, C=1024, K=588, Kp=608, T=G*G;
        wtrans_kernel<<<dim3((C+31)/32,(Kp+31)/32), dim3(32,8)>>>(wt[0], p_wtA, K, C, Kp);
        wtrans_kernel<<<dim3((NHID+31)/32,(C+31)/32), dim3(32,8)>>>(wp[0], p_wtB, C, NHID, C);
        im2col_kernel<<<dim3((T*Kp + 255)/256, 1, NB), 256>>>(x, p_patch, p_w, S, P, G, K, Kp);
        tgemm_kernel<false><<<dim3(C/128,(T+127)/128,NB), tb, TGEMM_SMEM>>>(
            p_patch, p_wtA, bt[0], p_feat, p_w, T, C, Kp);
        tgemm_kernel<true><<<dim3(NHID/128,(T+127)/128,NB), tb, TGEMM_SMEM>>>(
            p_feat, p_wtB, bp[0], out, p_w, T, NHID, C);
    }

    // ---------------- expert 1: S=336 P=14 G=24 C=768 -----------------------
    {
        const int S=336, P=14, G=24, C=768, K=588, Kp=608, T=G*G;
        resize_in_kernel<<<dim3((3*336*336 + 255)/256, 1, NB), 256>>>(x, p_x336, p_w + NB);
        wtrans_kernel<<<dim3((C+31)/32,(Kp+31)/32), dim3(32,8)>>>(wt[1], p_wtA, K, C, Kp);
        wtrans_kernel<<<dim3((NHID+31)/32,(C+31)/32), dim3(32,8)>>>(wp[1], p_wtB, C, NHID, C);
        im2col_kernel<<<dim3((T*Kp + 255)/256, 1, NB), 256>>>(p_x336, p_patch, p_w + NB, S, P, G, K, Kp);
        tgemm_kernel<false><<<dim3(C/128,(T+127)/128,NB), tb, TGEMM_SMEM>>>(
            p_patch, p_wtA, bt[1], p_feat, p_w + NB, T, C, Kp);
        tgemm_kernel<false><<<dim3(NHID/128,(T+127)/128,NB), tb, TGEMM_SMEM>>>(
            p_feat, p_wtB, bp[1], p_proj, p_w + NB, T, NHID, C);
        combine_kernel<<<dim3(1024, 1, NB), 256>>>(p_proj, out, p_w + NB, G);
    }

    // ---------------- expert 2: S=448 P=32 G=14 C=1152 ----------------------
    {
        const int S=448, P=32, G=14, C=1152, K=3072, Kp=3072, T=G*G;
        wtrans_kernel<<<dim3((C+31)/32,(Kp+31)/32), dim3(32,8)>>>(wt[2], p_wtA, K, C, Kp);
        wtrans_kernel<<<dim3((NHID+31)/32,(C+31)/32), dim3(32,8)>>>(wp[2], p_wtB, C, NHID, C);
        im2col_kernel<<<dim3((T*Kp + 255)/256, 1, NB), 256>>>(x, p_patch, p_w + 2*NB, S, P, G, K, Kp);
        tgemm_kernel<false><<<dim3(C/128,(T+127)/128,NB), tb, TGEMM_SMEM>>>(
            p_patch, p_wtA, bt[2], p_feat, p_w + 2*NB, T, C, Kp);
        tgemm_kernel<false><<<dim3(NHID/128,(T+127)/128,NB), tb, TGEMM_SMEM>>>(
            p_feat, p_wtB, bp[2], p_proj, p_w + 2*NB, T, NHID, C);
        combine_kernel<<<dim3(1024, 1, NB), 256>>>(p_proj, out, p_w + 2*NB, G);
    }
}